// round 13
// baseline (speedup 1.0000x reference)
#include <cuda_runtime.h>
#include <cuda_fp16.h>
#include <cstdint>

#define N_NODES 50000
#define N_EDGES 400000
#define EMB 384
#define EMB2 768
#define NLAYER 5
#define NUM_GRAPHS 128
#define BN_EPS 1e-5f
#define GOFF (NUM_GRAPHS * EMB)
#define NBLK 196   // ceil(50000/256)

// ---------------- scratch (device globals) ----------------------------------
__device__ float g_h [N_NODES * EMB];    // layer-0 encoder output
__device__ float g_z2[N_NODES * EMB2];   // GEMM1 output (pre-BN)
__device__ float g_z1[N_NODES * EMB];    // GEMM2 output (pre-BN)
__device__ float g_ecombo[512 * EMB];
__device__ __half g_Ahi[N_NODES * EMB2];
__device__ __half g_Alo[N_NODES * EMB2];
__device__ __half g_W1t_hi[NLAYER * EMB2 * EMB];
__device__ __half g_W1t_lo[NLAYER * EMB2 * EMB];
__device__ __half g_W2t_hi[NLAYER * EMB * EMB2];
__device__ __half g_W2t_lo[NLAYER * EMB * EMB2];
__device__ int   g_deg[N_NODES];
__device__ int   g_rowptr[N_NODES + 1];
__device__ int   g_cursor[N_NODES];
__device__ int   g_csr_src[N_EDGES];
__device__ int   g_csr_cid[N_EDGES];
__device__ int   g_bsum[NBLK];
__device__ int   g_boff[NBLK];
__device__ float g_sum[EMB2];
__device__ float g_sumsq[EMB2];
__device__ int   g_gstart[NUM_GRAPHS + 1];

// ---------------- PTX helpers (sm_80-level only) -----------------------------
__device__ __forceinline__ uint32_t smem_u32(const void* p) {
    uint32_t a;
    asm("{ .reg .u64 t; cvta.to.shared.u64 t, %1; cvt.u32.u64 %0, t; }" : "=r"(a) : "l"(p));
    return a;
}
__device__ __forceinline__ void cp16(uint32_t dst, const void* src, int valid) {
    asm volatile("cp.async.ca.shared.global [%0], [%1], 16, %2;"
                 :: "r"(dst), "l"(src), "r"(valid ? 16 : 0));
}
__device__ __forceinline__ void cp_commit() {
    asm volatile("cp.async.commit_group;" ::: "memory");
}
__device__ __forceinline__ void cp_wait1() {
    asm volatile("cp.async.wait_group 1;" ::: "memory");
}
__device__ __forceinline__ void ldsm_x4(uint32_t& r0, uint32_t& r1, uint32_t& r2,
                                        uint32_t& r3, uint32_t addr) {
    asm volatile("ldmatrix.sync.aligned.m8n8.x4.shared.b16 {%0,%1,%2,%3}, [%4];"
                 : "=r"(r0), "=r"(r1), "=r"(r2), "=r"(r3) : "r"(addr));
}
__device__ __forceinline__ void mma_f32acc(float* d, const uint32_t* a, const uint32_t* b) {
    asm volatile(
        "mma.sync.aligned.m16n8k16.row.col.f32.f16.f16.f32 "
        "{%0,%1,%2,%3}, {%4,%5,%6,%7}, {%8,%9}, {%0,%1,%2,%3};"
        : "+f"(d[0]), "+f"(d[1]), "+f"(d[2]), "+f"(d[3])
        : "r"(a[0]), "r"(a[1]), "r"(a[2]), "r"(a[3]), "r"(b[0]), "r"(b[1]));
}

// BN scale/shift from raw stats (inline finalize)
__device__ __forceinline__ void bn_coeff(int c, const float* __restrict__ gamma,
                                         const float* __restrict__ beta,
                                         float& sc, float& sh) {
    float m = g_sum[c] * (1.f / N_NODES);
    float v = g_sumsq[c] * (1.f / N_NODES) - m * m;
    float inv = rsqrtf(v + BN_EPS);
    sc = gamma[c] * inv;
    sh = beta[c] - sc * m;
}

// ---------------- encoders ---------------------------------------------------
__global__ void encode_nodes(const int* __restrict__ x,
                             const float* __restrict__ atom_emb) {
    int n = blockIdx.x, t = threadIdx.x;   // 96 threads, float4 lanes
    __shared__ int xs[9];
    if (t < 9) xs[t] = x[n * 9 + t];
    __syncthreads();
    float4 s = make_float4(0.f, 0.f, 0.f, 0.f);
#pragma unroll
    for (int k = 0; k < 9; k++) {
        const float4* row = (const float4*)(atom_emb + (size_t)((k << 6) + xs[k]) * EMB);
        float4 v = row[t];
        s.x += v.x; s.y += v.y; s.z += v.z; s.w += v.w;
    }
    ((float4*)g_h)[(size_t)n * 96 + t] = s;
}

__global__ void build_ecombo(const float* __restrict__ bond_emb) {
    int c = blockIdx.x;      // 0..511
    int t = threadIdx.x;     // 384
    int e0 = c >> 6, e1 = (c >> 3) & 7, e2 = c & 7;
    g_ecombo[c * EMB + t] = bond_emb[e0 * EMB + t]
                          + bond_emb[(8 + e1) * EMB + t]
                          + bond_emb[(16 + e2) * EMB + t];
}

// ---------------- CSR build (parallel scan) ------------------------------------
__global__ void zero_deg() {
    int i = blockIdx.x * blockDim.x + threadIdx.x;
    if (i < N_NODES) g_deg[i] = 0;
}
__global__ void count_deg(const int* __restrict__ ei) {
    int e = blockIdx.x * blockDim.x + threadIdx.x;
    if (e < N_EDGES) atomicAdd(&g_deg[ei[N_EDGES + e]], 1);
}
__global__ void deg_partial() {
    __shared__ int red[256];
    int i = blockIdx.x * 256 + threadIdx.x;
    red[threadIdx.x] = (i < N_NODES) ? g_deg[i] : 0;
    __syncthreads();
    for (int off = 128; off > 0; off >>= 1) {
        if (threadIdx.x < off) red[threadIdx.x] += red[threadIdx.x + off];
        __syncthreads();
    }
    if (threadIdx.x == 0) g_bsum[blockIdx.x] = red[0];
}
__global__ void bsum_scan() {
    __shared__ int v[256];
    int t = threadIdx.x;
    v[t] = (t < NBLK) ? g_bsum[t] : 0;
    __syncthreads();
    for (int off = 1; off < 256; off <<= 1) {
        int x = (t >= off) ? v[t - off] : 0;
        __syncthreads();
        v[t] += x;
        __syncthreads();
    }
    if (t < NBLK) g_boff[t] = (t == 0) ? 0 : v[t - 1];
    if (t == 0) g_rowptr[N_NODES] = v[NBLK - 1];
}
__global__ void rowptr_write() {
    __shared__ int v[256];
    int t = threadIdx.x;
    int i = blockIdx.x * 256 + t;
    int d = (i < N_NODES) ? g_deg[i] : 0;
    v[t] = d;
    __syncthreads();
    for (int off = 1; off < 256; off <<= 1) {
        int x = (t >= off) ? v[t - off] : 0;
        __syncthreads();
        v[t] += x;
        __syncthreads();
    }
    if (i < N_NODES) {
        int r = g_boff[blockIdx.x] + v[t] - d;
        g_rowptr[i] = r;
        g_cursor[i] = r;
    }
}
__global__ void fill_csr(const int* __restrict__ ei, const int* __restrict__ ea) {
    int e = blockIdx.x * blockDim.x + threadIdx.x;
    if (e >= N_EDGES) return;
    int dst = ei[N_EDGES + e];
    int pos = atomicAdd(&g_cursor[dst], 1);
    g_csr_src[pos] = ei[e];
    g_csr_cid[pos] = (ea[e * 3] << 6) | (ea[e * 3 + 1] << 3) | ea[e * 3 + 2];
}

// -------- aggregation with fused outer BN+ReLU (inline finalize) -------------
__device__ __forceinline__ float4 relu4_add(float4 h, float4 e) {
    float4 r;
    r.x = fmaxf(h.x + e.x, 0.f);
    r.y = fmaxf(h.y + e.y, 0.f);
    r.z = fmaxf(h.z + e.z, 0.f);
    r.w = fmaxf(h.w + e.w, 0.f);
    return r;
}
__global__ void aggregate(const float* __restrict__ src, int use_bn,
                          const float* __restrict__ gamma,
                          const float* __restrict__ beta) {
    int n = blockIdx.x, t = threadIdx.x;   // 96 threads, float4 lanes
    const float4* h4 = (const float4*)src;
    const float4* e4 = (const float4*)g_ecombo;
    float4 sc, sh;
    if (use_bn) {
        int c = t * 4;
        bn_coeff(c,     gamma, beta, sc.x, sh.x);
        bn_coeff(c + 1, gamma, beta, sc.y, sh.y);
        bn_coeff(c + 2, gamma, beta, sc.z, sh.z);
        bn_coeff(c + 3, gamma, beta, sc.w, sh.w);
    }
    auto xf = [&](float4 z) -> float4 {
        if (use_bn) {
            z.x = fmaxf(sc.x * z.x + sh.x, 0.f);
            z.y = fmaxf(sc.y * z.y + sh.y, 0.f);
            z.z = fmaxf(sc.z * z.z + sh.z, 0.f);
            z.w = fmaxf(sc.w * z.w + sh.w, 0.f);
        }
        return z;
    };
    float4 a = xf(h4[(size_t)n * 96 + t]);
    int p = g_rowptr[n], p1 = g_rowptr[n + 1];
    for (; p + 1 < p1; p += 2) {
        int s0 = g_csr_src[p],     c0 = g_csr_cid[p];
        int s1 = g_csr_src[p + 1], c1 = g_csr_cid[p + 1];
        float4 hv0 = xf(h4[(size_t)s0 * 96 + t]);
        float4 ev0 = e4[(size_t)c0 * 96 + t];
        float4 hv1 = xf(h4[(size_t)s1 * 96 + t]);
        float4 ev1 = e4[(size_t)c1 * 96 + t];
        float4 m0 = relu4_add(hv0, ev0);
        float4 m1 = relu4_add(hv1, ev1);
        a.x += m0.x + m1.x; a.y += m0.y + m1.y;
        a.z += m0.z + m1.z; a.w += m0.w + m1.w;
    }
    if (p < p1) {
        int s0 = g_csr_src[p], c0 = g_csr_cid[p];
        float4 m0 = relu4_add(xf(h4[(size_t)s0 * 96 + t]), e4[(size_t)c0 * 96 + t]);
        a.x += m0.x; a.y += m0.y; a.z += m0.z; a.w += m0.w;
    }
    size_t base = (size_t)n * EMB + t * 4;
    float v[4] = {a.x, a.y, a.z, a.w};
    __half hi[4], lo[4];
#pragma unroll
    for (int j = 0; j < 4; j++) {
        hi[j] = __float2half(v[j]);
        lo[j] = __float2half(v[j] - __half2float(hi[j]));
    }
    *(__half2*)&g_Ahi[base]     = __halves2half2(hi[0], hi[1]);
    *(__half2*)&g_Ahi[base + 2] = __halves2half2(hi[2], hi[3]);
    *(__half2*)&g_Alo[base]     = __halves2half2(lo[0], lo[1]);
    *(__half2*)&g_Alo[base + 2] = __halves2half2(lo[2], lo[3]);
}

// ---------------- weight transpose + split (fp16) -----------------------------
__global__ void wsplit(const float* __restrict__ W, __half* __restrict__ Thi,
                       __half* __restrict__ Tlo, int K, int N) {
    __shared__ float t[32][33];
    int l = blockIdx.z;
    int n0 = blockIdx.x * 32, k0 = blockIdx.y * 32;
    const float* Wl = W + (size_t)l * K * N;
    for (int i = threadIdx.y; i < 32; i += 8)
        t[i][threadIdx.x] = Wl[(size_t)(k0 + i) * N + n0 + threadIdx.x];
    __syncthreads();
    __half* Hl = Thi + (size_t)l * K * N;
    __half* Ll = Tlo + (size_t)l * K * N;
    for (int i = threadIdx.y; i < 32; i += 8) {
        float v = t[threadIdx.x][i];
        __half hi = __float2half(v);
        Hl[(size_t)(n0 + i) * K + k0 + threadIdx.x] = hi;
        Ll[(size_t)(n0 + i) * K + k0 + threadIdx.x] =
            __float2half(v - __half2float(hi));
    }
}

// ---------------- HMMA fp16 split GEMM + fused BN column stats ----------------
#define BK 64
#define LDS_E 72
#define TILE_B (128 * LDS_E * 2)
#define STAGE_B (2 * TILE_B)
#define GEMM_SMEM (2 * STAGE_B)
__global__ __launch_bounds__(128, 2)
void gemm_mma(const __half* __restrict__ Ahi,
              const __half* __restrict__ Alo,
              const __half* __restrict__ Whi,
              const __half* __restrict__ Wlo,
              const float* __restrict__ bias,
              float* __restrict__ C,
              int M, int Ntot, int K) {
    extern __shared__ __align__(16) char smem[];
    __shared__ float s_sum[128];
    __shared__ float s_sq[128];
    uint32_t sb = smem_u32(smem);
    const int CPS = K / BK;
    const int NC  = 3 * CPS;
    int tid = threadIdx.x, wid = tid >> 5, lane = tid & 31;
    int r0 = blockIdx.y * 128;
    int n0 = blockIdx.x * 128;
    int wm = (wid & 1) * 64;
    int wn = (wid >> 1) * 64;

    if (tid < 128) { s_sum[tid] = 0.f; s_sq[tid] = 0.f; }

    int ldr = tid >> 1;
    int lde = (tid & 1) * 32;

    auto prefetch = [&](int c, int stage) {
        int seg = c / CPS;
        int kc = (c - seg * CPS) * BK;
        const __half* Ap = (seg == 1) ? Alo : Ahi;
        const __half* Bp = (seg == 2) ? Wlo : Whi;
        uint32_t abase = sb + stage * STAGE_B;
        uint32_t bbase = abase + TILE_B;
#pragma unroll
        for (int h = 0; h < 2; h++) {
            int row = ldr + h * 64;
            int ar = r0 + row;
            int av = ar < M;
            const __half* asrc = Ap + (size_t)ar * K + kc + lde;
            uint32_t adst = abase + (row * LDS_E + lde) * 2;
            const __half* bsrc = Bp + (size_t)(n0 + row) * K + kc + lde;
            uint32_t bdst = bbase + (row * LDS_E + lde) * 2;
#pragma unroll
            for (int i = 0; i < 4; i++) {
                cp16(adst + i * 16, asrc + i * 8, av);
                cp16(bdst + i * 16, bsrc + i * 8, 1);
            }
        }
    };

    float acc[4][8][4];
#pragma unroll
    for (int i = 0; i < 4; i++)
#pragma unroll
        for (int j = 0; j < 8; j++)
#pragma unroll
            for (int q = 0; q < 4; q++) acc[i][j][q] = 0.f;

    prefetch(0, 0); cp_commit();

    for (int c = 0; c < NC; c++) {
        if (c + 1 < NC) prefetch(c + 1, (c + 1) & 1);
        cp_commit();
        cp_wait1();
        __syncthreads();

        uint32_t abase = sb + (c & 1) * STAGE_B;
        uint32_t bbase = abase + TILE_B;
#pragma unroll
        for (int ks = 0; ks < 4; ks++) {
            int k0 = ks * 16;
            uint32_t af[4][4];
#pragma unroll
            for (int i = 0; i < 4; i++) {
                uint32_t addr = abase +
                    ((wm + i * 16 + (lane & 15)) * LDS_E + k0 + (lane >> 4) * 8) * 2;
                ldsm_x4(af[i][0], af[i][1], af[i][2], af[i][3], addr);
            }
            uint32_t bf[4][4];
#pragma unroll
            for (int p = 0; p < 4; p++) {
                uint32_t addr = bbase +
                    ((wn + p * 16 + (lane & 7) + ((lane >> 4) & 1) * 8) * LDS_E
                     + k0 + ((lane >> 3) & 1) * 8) * 2;
                ldsm_x4(bf[p][0], bf[p][1], bf[p][2], bf[p][3], addr);
            }
#pragma unroll
            for (int i = 0; i < 4; i++)
#pragma unroll
                for (int j = 0; j < 8; j++) {
                    uint32_t bb[2] = { bf[j >> 1][(j & 1) * 2],
                                       bf[j >> 1][(j & 1) * 2 + 1] };
                    mma_f32acc(acc[i][j], af[i], bb);
                }
        }
        __syncthreads();
    }

#pragma unroll
    for (int j = 0; j < 8; j++) {
        int cloc = wn + j * 8 + (lane & 3) * 2;
        int col = n0 + cloc;
        float bx = bias[col], by = bias[col + 1];
        float s0 = 0.f, s1 = 0.f, q0 = 0.f, q1 = 0.f;
#pragma unroll
        for (int i = 0; i < 4; i++) {
            int ra = r0 + wm + i * 16 + (lane >> 2);
            int rb = ra + 8;
            if (ra < M) {
                float v0 = acc[i][j][0] + bx, v1 = acc[i][j][1] + by;
                *(float2*)(C + (size_t)ra * Ntot + col) = make_float2(v0, v1);
                s0 += v0; q0 += v0 * v0; s1 += v1; q1 += v1 * v1;
            }
            if (rb < M) {
                float v2 = acc[i][j][2] + bx, v3 = acc[i][j][3] + by;
                *(float2*)(C + (size_t)rb * Ntot + col) = make_float2(v2, v3);
                s0 += v2; q0 += v2 * v2; s1 += v3; q1 += v3 * v3;
            }
        }
#pragma unroll
        for (int off = 4; off <= 16; off <<= 1) {
            s0 += __shfl_xor_sync(0xFFFFFFFFu, s0, off);
            s1 += __shfl_xor_sync(0xFFFFFFFFu, s1, off);
            q0 += __shfl_xor_sync(0xFFFFFFFFu, q0, off);
            q1 += __shfl_xor_sync(0xFFFFFFFFu, q1, off);
        }
        if (lane < 4) {
            atomicAdd(&s_sum[cloc],     s0);
            atomicAdd(&s_sum[cloc + 1], s1);
            atomicAdd(&s_sq[cloc],      q0);
            atomicAdd(&s_sq[cloc + 1],  q1);
        }
    }
    __syncthreads();
    if (tid < 128) {
        atomicAdd(&g_sum[n0 + tid],   s_sum[tid]);
        atomicAdd(&g_sumsq[n0 + tid], s_sq[tid]);
    }
}

// ---------------- BN+ReLU + fp16 split (inline finalize) ----------------------
__global__ void bnrelu_split(const float* __restrict__ Z,
                             __half* __restrict__ Hi,
                             __half* __restrict__ Lo,
                             const float* __restrict__ gamma,
                             const float* __restrict__ beta, int C4) {
    int total = N_NODES * C4;
    for (int i4 = blockIdx.x * blockDim.x + threadIdx.x; i4 < total;
         i4 += gridDim.x * blockDim.x) {
        int col = (i4 % C4) * 4;
        float sc0, sh0, sc1, sh1, sc2, sh2, sc3, sh3;
        bn_coeff(col,     gamma, beta, sc0, sh0);
        bn_coeff(col + 1, gamma, beta, sc1, sh1);
        bn_coeff(col + 2, gamma, beta, sc2, sh2);
        bn_coeff(col + 3, gamma, beta, sc3, sh3);
        float4 z = ((const float4*)Z)[i4];
        float v[4];
        v[0] = fmaxf(sc0 * z.x + sh0, 0.f);
        v[1] = fmaxf(sc1 * z.y + sh1, 0.f);
        v[2] = fmaxf(sc2 * z.z + sh2, 0.f);
        v[3] = fmaxf(sc3 * z.w + sh3, 0.f);
        __half hi[4], lo[4];
#pragma unroll
        for (int j = 0; j < 4; j++) {
            hi[j] = __float2half(v[j]);
            lo[j] = __float2half(v[j] - __half2float(hi[j]));
        }
        size_t base = (size_t)i4 * 4;
        *(__half2*)&Hi[base]     = __halves2half2(hi[0], hi[1]);
        *(__half2*)&Hi[base + 2] = __halves2half2(hi[2], hi[3]);
        *(__half2*)&Lo[base]     = __halves2half2(lo[0], lo[1]);
        *(__half2*)&Lo[base + 2] = __halves2half2(lo[2], lo[3]);
    }
}

// last layer only: h = relu(bn(z1)) -> d_out (GOFF region), inline finalize
__global__ void bnrelu_out(const float* __restrict__ Z, float* __restrict__ O1,
                           const float* __restrict__ gamma,
                           const float* __restrict__ beta) {
    const int C4 = EMB / 4;
    int total = N_NODES * C4;
    for (int i4 = blockIdx.x * blockDim.x + threadIdx.x; i4 < total;
         i4 += gridDim.x * blockDim.x) {
        int col = (i4 % C4) * 4;
        float sc0, sh0, sc1, sh1, sc2, sh2, sc3, sh3;
        bn_coeff(col,     gamma, beta, sc0, sh0);
        bn_coeff(col + 1, gamma, beta, sc1, sh1);
        bn_coeff(col + 2, gamma, beta, sc2, sh2);
        bn_coeff(col + 3, gamma, beta, sc3, sh3);
        float4 z = ((const float4*)Z)[i4];
        float4 o;
        o.x = fmaxf(sc0 * z.x + sh0, 0.f);
        o.y = fmaxf(sc1 * z.y + sh1, 0.f);
        o.z = fmaxf(sc2 * z.z + sh2, 0.f);
        o.w = fmaxf(sc3 * z.w + sh3, 0.f);
        ((float4*)O1)[i4] = o;
    }
}

// ---------------- pooling -------------------------------------------------------
__global__ void boundaries_kernel(const int* __restrict__ batch) {
    int g = threadIdx.x;
    if (g < NUM_GRAPHS) {
        int lo = 0, hi = N_NODES;
        while (lo < hi) {
            int mid = (lo + hi) >> 1;
            if (batch[mid] < g) lo = mid + 1; else hi = mid;
        }
        g_gstart[g] = lo;
    }
    if (g == 0) g_gstart[NUM_GRAPHS] = N_NODES;
}
__global__ void pool(const float* __restrict__ h, float* __restrict__ out) {
    int g = blockIdx.x, t = threadIdx.x;
    int s = g_gstart[g], e = g_gstart[g + 1];
    float a0 = 0.f, a1 = 0.f, a2 = 0.f;
    for (int r = s; r < e; r++) {
        const float* hr = h + (size_t)r * EMB;
        a0 += hr[t]; a1 += hr[t + 128]; a2 += hr[t + 256];
    }
    float* o = out + (size_t)g * EMB;
    o[t] = a0; o[t + 128] = a1; o[t + 256] = a2;
}

// ---------------- launch ----------------------------------------------------------
extern "C" void kernel_launch(void* const* d_in, const int* in_sizes, int n_in,
                              void* d_out, int out_size) {
    const int*   batch    = (const int*)d_in[0];
    const int*   x        = (const int*)d_in[1];
    const int*   ei       = (const int*)d_in[2];
    const int*   ea       = (const int*)d_in[3];
    const float* atom_emb = (const float*)d_in[4];
    const float* bond_emb = (const float*)d_in[5];
    const float* W1       = (const float*)d_in[6];
    const float* b1       = (const float*)d_in[7];
    const float* g1       = (const float*)d_in[8];
    const float* be1      = (const float*)d_in[9];
    const float* W2       = (const float*)d_in[10];
    const float* b2       = (const float*)d_in[11];
    const float* gbn      = (const float*)d_in[12];
    const float* bbn      = (const float*)d_in[13];
    float* out = (float*)d_out;

    float* g_h_p;   cudaGetSymbolAddress((void**)&g_h_p,  g_h);
    float* g_z1_p;  cudaGetSymbolAddress((void**)&g_z1_p, g_z1);
    float* g_z2_p;  cudaGetSymbolAddress((void**)&g_z2_p, g_z2);
    float* g_sum_p;   cudaGetSymbolAddress((void**)&g_sum_p,   g_sum);
    float* g_sumsq_p; cudaGetSymbolAddress((void**)&g_sumsq_p, g_sumsq);
    __half *Ahi_p, *Alo_p, *W1h_p, *W1l_p, *W2h_p, *W2l_p;
    cudaGetSymbolAddress((void**)&Ahi_p, g_Ahi);
    cudaGetSymbolAddress((void**)&Alo_p, g_Alo);
    cudaGetSymbolAddress((void**)&W1h_p, g_W1t_hi);
    cudaGetSymbolAddress((void**)&W1l_p, g_W1t_lo);
    cudaGetSymbolAddress((void**)&W2h_p, g_W2t_hi);
    cudaGetSymbolAddress((void**)&W2l_p, g_W2t_lo);

    cudaFuncSetAttribute(gemm_mma, cudaFuncAttributeMaxDynamicSharedMemorySize,
                         GEMM_SMEM);

    encode_nodes<<<N_NODES, 96>>>(x, atom_emb);
    build_ecombo<<<512, EMB>>>(bond_emb);

    zero_deg<<<NBLK, 256>>>();
    count_deg<<<(N_EDGES + 255) / 256, 256>>>(ei);
    deg_partial<<<NBLK, 256>>>();
    bsum_scan<<<1, 256>>>();
    rowptr_write<<<NBLK, 256>>>();
    fill_csr<<<(N_EDGES + 255) / 256, 256>>>(ei, ea);

    {
        dim3 g1d(EMB2 / 32, EMB / 32, NLAYER);
        wsplit<<<g1d, dim3(32, 8)>>>(W1, W1h_p, W1l_p, EMB, EMB2);
        dim3 g2d(EMB / 32, EMB2 / 32, NLAYER);
        wsplit<<<g2d, dim3(32, 8)>>>(W2, W2h_p, W2l_p, EMB2, EMB);
    }

    const int MT = (N_NODES + 127) / 128;  // 391
    const int EW_BLOCKS = 2368;

    for (int l = 0; l < NLAYER; l++) {
        // gather + fused outer-BN transform of previous layer (l>0)
        aggregate<<<N_NODES, 96>>>(l == 0 ? g_h_p : g_z1_p, l > 0,
                                   gbn + (l > 0 ? (l - 1) : 0) * EMB,
                                   bbn + (l > 0 ? (l - 1) : 0) * EMB);

        cudaMemsetAsync(g_sum_p,   0, EMB2 * sizeof(float));
        cudaMemsetAsync(g_sumsq_p, 0, EMB2 * sizeof(float));
        gemm_mma<<<dim3(EMB2 / 128, MT), 128, GEMM_SMEM>>>(
            Ahi_p, Alo_p,
            W1h_p + (size_t)l * EMB2 * EMB, W1l_p + (size_t)l * EMB2 * EMB,
            b1 + l * EMB2, g_z2_p, N_NODES, EMB2, EMB);
        bnrelu_split<<<EW_BLOCKS, 256>>>(g_z2_p, Ahi_p, Alo_p,
                                         g1 + l * EMB2, be1 + l * EMB2, EMB2 / 4);

        cudaMemsetAsync(g_sum_p,   0, EMB2 * sizeof(float));
        cudaMemsetAsync(g_sumsq_p, 0, EMB2 * sizeof(float));
        gemm_mma<<<dim3(EMB / 128, MT), 128, GEMM_SMEM>>>(
            Ahi_p, Alo_p,
            W2h_p + (size_t)l * EMB * EMB2, W2l_p + (size_t)l * EMB * EMB2,
            b2 + l * EMB, g_z1_p, N_NODES, EMB, EMB2);
        // next aggregate applies the outer BN (layer l) on the fly
    }

    // final h = relu(bn(z1)) written once, directly into d_out
    bnrelu_out<<<EW_BLOCKS, 256>>>(g_z1_p, out + GOFF,
                                   gbn + (NLAYER - 1) * EMB, bbn + (NLAYER - 1) * EMB);
    boundaries_kernel<<<1, 128>>>(batch);
    pool<<<NUM_GRAPHS, 128>>>(out + GOFF, out);
}

// round 14
// speedup vs baseline: 1.0703x; 1.0703x over previous
#include <cuda_runtime.h>
#include <cuda_fp16.h>
#include <cstdint>

#define N_NODES 50000
#define N_EDGES 400000
#define EMB 384
#define EMB2 768
#define NLAYER 5
#define NUM_GRAPHS 128
#define BN_EPS 1e-5f
#define GOFF (NUM_GRAPHS * EMB)
#define NBLK 196   // ceil(50000/256)

// ---------------- scratch (device globals) ----------------------------------
__device__ float g_h [N_NODES * EMB];    // layer-0 encoder output
__device__ float g_z2[N_NODES * EMB2];   // GEMM1 output (pre-BN)
__device__ float g_z1[N_NODES * EMB];    // GEMM2 output (pre-BN)
__device__ float g_ecombo[512 * EMB];
__device__ __half g_Ahi[N_NODES * EMB2];
__device__ __half g_Alo[N_NODES * EMB2];
__device__ __half g_W1t_hi[NLAYER * EMB2 * EMB];
__device__ __half g_W1t_lo[NLAYER * EMB2 * EMB];
__device__ __half g_W2t_hi[NLAYER * EMB * EMB2];
__device__ __half g_W2t_lo[NLAYER * EMB * EMB2];
__device__ int   g_deg[N_NODES];
__device__ int   g_rowptr[N_NODES + 1];
__device__ int   g_cursor[N_NODES];
__device__ int   g_csr_src[N_EDGES];
__device__ int   g_csr_cid[N_EDGES];
__device__ int   g_bsum[NBLK];
__device__ int   g_boff[NBLK];
__device__ float g_sum[EMB2];
__device__ float g_sumsq[EMB2];
__device__ float g_scale[EMB2];
__device__ float g_shift[EMB2];
__device__ int   g_gstart[NUM_GRAPHS + 1];

// ---------------- PTX helpers (sm_80-level only) -----------------------------
__device__ __forceinline__ uint32_t smem_u32(const void* p) {
    uint32_t a;
    asm("{ .reg .u64 t; cvta.to.shared.u64 t, %1; cvt.u32.u64 %0, t; }" : "=r"(a) : "l"(p));
    return a;
}
__device__ __forceinline__ void cp16(uint32_t dst, const void* src, int valid) {
    asm volatile("cp.async.ca.shared.global [%0], [%1], 16, %2;"
                 :: "r"(dst), "l"(src), "r"(valid ? 16 : 0));
}
__device__ __forceinline__ void cp_commit() {
    asm volatile("cp.async.commit_group;" ::: "memory");
}
__device__ __forceinline__ void cp_wait1() {
    asm volatile("cp.async.wait_group 1;" ::: "memory");
}
__device__ __forceinline__ void ldsm_x4(uint32_t& r0, uint32_t& r1, uint32_t& r2,
                                        uint32_t& r3, uint32_t addr) {
    asm volatile("ldmatrix.sync.aligned.m8n8.x4.shared.b16 {%0,%1,%2,%3}, [%4];"
                 : "=r"(r0), "=r"(r1), "=r"(r2), "=r"(r3) : "r"(addr));
}
__device__ __forceinline__ void mma_f32acc(float* d, const uint32_t* a, const uint32_t* b) {
    asm volatile(
        "mma.sync.aligned.m16n8k16.row.col.f32.f16.f16.f32 "
        "{%0,%1,%2,%3}, {%4,%5,%6,%7}, {%8,%9}, {%0,%1,%2,%3};"
        : "+f"(d[0]), "+f"(d[1]), "+f"(d[2]), "+f"(d[3])
        : "r"(a[0]), "r"(a[1]), "r"(a[2]), "r"(a[3]), "r"(b[0]), "r"(b[1]));
}

// ---------------- encoders ---------------------------------------------------
__global__ void encode_nodes(const int* __restrict__ x,
                             const float* __restrict__ atom_emb) {
    int n = blockIdx.x, t = threadIdx.x;   // 96 threads, float4 lanes
    __shared__ int xs[9];
    if (t < 9) xs[t] = x[n * 9 + t];
    __syncthreads();
    float4 s = make_float4(0.f, 0.f, 0.f, 0.f);
#pragma unroll
    for (int k = 0; k < 9; k++) {
        const float4* row = (const float4*)(atom_emb + (size_t)((k << 6) + xs[k]) * EMB);
        float4 v = row[t];
        s.x += v.x; s.y += v.y; s.z += v.z; s.w += v.w;
    }
    ((float4*)g_h)[(size_t)n * 96 + t] = s;
}

__global__ void build_ecombo(const float* __restrict__ bond_emb) {
    int c = blockIdx.x;      // 0..511
    int t = threadIdx.x;     // 384
    int e0 = c >> 6, e1 = (c >> 3) & 7, e2 = c & 7;
    g_ecombo[c * EMB + t] = bond_emb[e0 * EMB + t]
                          + bond_emb[(8 + e1) * EMB + t]
                          + bond_emb[(16 + e2) * EMB + t];
}

// ---------------- CSR build (parallel scan) ------------------------------------
__global__ void zero_deg() {
    int i = blockIdx.x * blockDim.x + threadIdx.x;
    if (i < N_NODES) g_deg[i] = 0;
}
__global__ void count_deg(const int* __restrict__ ei) {
    int e = blockIdx.x * blockDim.x + threadIdx.x;
    if (e < N_EDGES) atomicAdd(&g_deg[ei[N_EDGES + e]], 1);
}
__global__ void deg_partial() {
    __shared__ int red[256];
    int i = blockIdx.x * 256 + threadIdx.x;
    red[threadIdx.x] = (i < N_NODES) ? g_deg[i] : 0;
    __syncthreads();
    for (int off = 128; off > 0; off >>= 1) {
        if (threadIdx.x < off) red[threadIdx.x] += red[threadIdx.x + off];
        __syncthreads();
    }
    if (threadIdx.x == 0) g_bsum[blockIdx.x] = red[0];
}
__global__ void bsum_scan() {
    __shared__ int v[256];
    int t = threadIdx.x;
    v[t] = (t < NBLK) ? g_bsum[t] : 0;
    __syncthreads();
    for (int off = 1; off < 256; off <<= 1) {
        int x = (t >= off) ? v[t - off] : 0;
        __syncthreads();
        v[t] += x;
        __syncthreads();
    }
    if (t < NBLK) g_boff[t] = (t == 0) ? 0 : v[t - 1];
    if (t == 0) g_rowptr[N_NODES] = v[NBLK - 1];
}
__global__ void rowptr_write() {
    __shared__ int v[256];
    int t = threadIdx.x;
    int i = blockIdx.x * 256 + t;
    int d = (i < N_NODES) ? g_deg[i] : 0;
    v[t] = d;
    __syncthreads();
    for (int off = 1; off < 256; off <<= 1) {
        int x = (t >= off) ? v[t - off] : 0;
        __syncthreads();
        v[t] += x;
        __syncthreads();
    }
    if (i < N_NODES) {
        int r = g_boff[blockIdx.x] + v[t] - d;
        g_rowptr[i] = r;
        g_cursor[i] = r;
    }
}
__global__ void fill_csr(const int* __restrict__ ei, const int* __restrict__ ea) {
    int e = blockIdx.x * blockDim.x + threadIdx.x;
    if (e >= N_EDGES) return;
    int dst = ei[N_EDGES + e];
    int pos = atomicAdd(&g_cursor[dst], 1);
    g_csr_src[pos] = ei[e];
    g_csr_cid[pos] = (ea[e * 3] << 6) | (ea[e * 3 + 1] << 3) | ea[e * 3 + 2];
}

// -------- aggregation with fused outer BN+ReLU on the gathered reads ---------
__device__ __forceinline__ float4 relu4_add(float4 h, float4 e) {
    float4 r;
    r.x = fmaxf(h.x + e.x, 0.f);
    r.y = fmaxf(h.y + e.y, 0.f);
    r.z = fmaxf(h.z + e.z, 0.f);
    r.w = fmaxf(h.w + e.w, 0.f);
    return r;
}
__global__ void aggregate(const float* __restrict__ src, int use_bn) {
    int n = blockIdx.x, t = threadIdx.x;   // 96 threads, float4 lanes
    const float4* h4 = (const float4*)src;
    const float4* e4 = (const float4*)g_ecombo;
    float4 sc, sh;
    if (use_bn) {
        sc = ((const float4*)g_scale)[t];
        sh = ((const float4*)g_shift)[t];
    }
    auto xf = [&](float4 z) -> float4 {
        if (use_bn) {
            z.x = fmaxf(sc.x * z.x + sh.x, 0.f);
            z.y = fmaxf(sc.y * z.y + sh.y, 0.f);
            z.z = fmaxf(sc.z * z.z + sh.z, 0.f);
            z.w = fmaxf(sc.w * z.w + sh.w, 0.f);
        }
        return z;
    };
    float4 a = xf(h4[(size_t)n * 96 + t]);
    int p = g_rowptr[n], p1 = g_rowptr[n + 1];
    for (; p + 3 < p1; p += 4) {
        int s0 = g_csr_src[p],     c0 = g_csr_cid[p];
        int s1 = g_csr_src[p + 1], c1 = g_csr_cid[p + 1];
        int s2 = g_csr_src[p + 2], c2 = g_csr_cid[p + 2];
        int s3 = g_csr_src[p + 3], c3 = g_csr_cid[p + 3];
        float4 hv0 = h4[(size_t)s0 * 96 + t], ev0 = e4[(size_t)c0 * 96 + t];
        float4 hv1 = h4[(size_t)s1 * 96 + t], ev1 = e4[(size_t)c1 * 96 + t];
        float4 hv2 = h4[(size_t)s2 * 96 + t], ev2 = e4[(size_t)c2 * 96 + t];
        float4 hv3 = h4[(size_t)s3 * 96 + t], ev3 = e4[(size_t)c3 * 96 + t];
        float4 m0 = relu4_add(xf(hv0), ev0);
        float4 m1 = relu4_add(xf(hv1), ev1);
        float4 m2 = relu4_add(xf(hv2), ev2);
        float4 m3 = relu4_add(xf(hv3), ev3);
        a.x += (m0.x + m1.x) + (m2.x + m3.x);
        a.y += (m0.y + m1.y) + (m2.y + m3.y);
        a.z += (m0.z + m1.z) + (m2.z + m3.z);
        a.w += (m0.w + m1.w) + (m2.w + m3.w);
    }
    for (; p < p1; p++) {
        int s0 = g_csr_src[p], c0 = g_csr_cid[p];
        float4 m0 = relu4_add(xf(h4[(size_t)s0 * 96 + t]), e4[(size_t)c0 * 96 + t]);
        a.x += m0.x; a.y += m0.y; a.z += m0.z; a.w += m0.w;
    }
    size_t base = (size_t)n * EMB + t * 4;
    float v[4] = {a.x, a.y, a.z, a.w};
    __half hi[4], lo[4];
#pragma unroll
    for (int j = 0; j < 4; j++) {
        hi[j] = __float2half(v[j]);
        lo[j] = __float2half(v[j] - __half2float(hi[j]));
    }
    *(__half2*)&g_Ahi[base]     = __halves2half2(hi[0], hi[1]);
    *(__half2*)&g_Ahi[base + 2] = __halves2half2(hi[2], hi[3]);
    *(__half2*)&g_Alo[base]     = __halves2half2(lo[0], lo[1]);
    *(__half2*)&g_Alo[base + 2] = __halves2half2(lo[2], lo[3]);
}

// ---------------- weight transpose + split (fp16) -----------------------------
__global__ void wsplit(const float* __restrict__ W, __half* __restrict__ Thi,
                       __half* __restrict__ Tlo, int K, int N) {
    __shared__ float t[32][33];
    int l = blockIdx.z;
    int n0 = blockIdx.x * 32, k0 = blockIdx.y * 32;
    const float* Wl = W + (size_t)l * K * N;
    for (int i = threadIdx.y; i < 32; i += 8)
        t[i][threadIdx.x] = Wl[(size_t)(k0 + i) * N + n0 + threadIdx.x];
    __syncthreads();
    __half* Hl = Thi + (size_t)l * K * N;
    __half* Ll = Tlo + (size_t)l * K * N;
    for (int i = threadIdx.y; i < 32; i += 8) {
        float v = t[threadIdx.x][i];
        __half hi = __float2half(v);
        Hl[(size_t)(n0 + i) * K + k0 + threadIdx.x] = hi;
        Ll[(size_t)(n0 + i) * K + k0 + threadIdx.x] =
            __float2half(v - __half2float(hi));
    }
}

// ---------------- HMMA fp16 split GEMM + fused BN column stats ----------------
#define BK 64
#define LDS_E 72
#define TILE_B (128 * LDS_E * 2)
#define STAGE_B (2 * TILE_B)
#define GEMM_SMEM (2 * STAGE_B)
__global__ __launch_bounds__(128, 2)
void gemm_mma(const __half* __restrict__ Ahi,
              const __half* __restrict__ Alo,
              const __half* __restrict__ Whi,
              const __half* __restrict__ Wlo,
              const float* __restrict__ bias,
              float* __restrict__ C,
              int M, int Ntot, int K) {
    extern __shared__ __align__(16) char smem[];
    __shared__ float s_sum[128];
    __shared__ float s_sq[128];
    uint32_t sb = smem_u32(smem);
    const int CPS = K / BK;
    const int NC  = 3 * CPS;
    int tid = threadIdx.x, wid = tid >> 5, lane = tid & 31;
    int r0 = blockIdx.y * 128;
    int n0 = blockIdx.x * 128;
    int wm = (wid & 1) * 64;
    int wn = (wid >> 1) * 64;

    if (tid < 128) { s_sum[tid] = 0.f; s_sq[tid] = 0.f; }

    int ldr = tid >> 1;
    int lde = (tid & 1) * 32;

    auto prefetch = [&](int c, int stage) {
        int seg = c / CPS;
        int kc = (c - seg * CPS) * BK;
        const __half* Ap = (seg == 1) ? Alo : Ahi;
        const __half* Bp = (seg == 2) ? Wlo : Whi;
        uint32_t abase = sb + stage * STAGE_B;
        uint32_t bbase = abase + TILE_B;
#pragma unroll
        for (int h = 0; h < 2; h++) {
            int row = ldr + h * 64;
            int ar = r0 + row;
            int av = ar < M;
            const __half* asrc = Ap + (size_t)ar * K + kc + lde;
            uint32_t adst = abase + (row * LDS_E + lde) * 2;
            const __half* bsrc = Bp + (size_t)(n0 + row) * K + kc + lde;
            uint32_t bdst = bbase + (row * LDS_E + lde) * 2;
#pragma unroll
            for (int i = 0; i < 4; i++) {
                cp16(adst + i * 16, asrc + i * 8, av);
                cp16(bdst + i * 16, bsrc + i * 8, 1);
            }
        }
    };

    float acc[4][8][4];
#pragma unroll
    for (int i = 0; i < 4; i++)
#pragma unroll
        for (int j = 0; j < 8; j++)
#pragma unroll
            for (int q = 0; q < 4; q++) acc[i][j][q] = 0.f;

    prefetch(0, 0); cp_commit();

    for (int c = 0; c < NC; c++) {
        if (c + 1 < NC) prefetch(c + 1, (c + 1) & 1);
        cp_commit();
        cp_wait1();
        __syncthreads();

        uint32_t abase = sb + (c & 1) * STAGE_B;
        uint32_t bbase = abase + TILE_B;
#pragma unroll
        for (int ks = 0; ks < 4; ks++) {
            int k0 = ks * 16;
            uint32_t af[4][4];
#pragma unroll
            for (int i = 0; i < 4; i++) {
                uint32_t addr = abase +
                    ((wm + i * 16 + (lane & 15)) * LDS_E + k0 + (lane >> 4) * 8) * 2;
                ldsm_x4(af[i][0], af[i][1], af[i][2], af[i][3], addr);
            }
            uint32_t bf[4][4];
#pragma unroll
            for (int p = 0; p < 4; p++) {
                uint32_t addr = bbase +
                    ((wn + p * 16 + (lane & 7) + ((lane >> 4) & 1) * 8) * LDS_E
                     + k0 + ((lane >> 3) & 1) * 8) * 2;
                ldsm_x4(bf[p][0], bf[p][1], bf[p][2], bf[p][3], addr);
            }
#pragma unroll
            for (int i = 0; i < 4; i++)
#pragma unroll
                for (int j = 0; j < 8; j++) {
                    uint32_t bb[2] = { bf[j >> 1][(j & 1) * 2],
                                       bf[j >> 1][(j & 1) * 2 + 1] };
                    mma_f32acc(acc[i][j], af[i], bb);
                }
        }
        __syncthreads();
    }

#pragma unroll
    for (int j = 0; j < 8; j++) {
        int cloc = wn + j * 8 + (lane & 3) * 2;
        int col = n0 + cloc;
        float bx = bias[col], by = bias[col + 1];
        float s0 = 0.f, s1 = 0.f, q0 = 0.f, q1 = 0.f;
#pragma unroll
        for (int i = 0; i < 4; i++) {
            int ra = r0 + wm + i * 16 + (lane >> 2);
            int rb = ra + 8;
            if (ra < M) {
                float v0 = acc[i][j][0] + bx, v1 = acc[i][j][1] + by;
                *(float2*)(C + (size_t)ra * Ntot + col) = make_float2(v0, v1);
                s0 += v0; q0 += v0 * v0; s1 += v1; q1 += v1 * v1;
            }
            if (rb < M) {
                float v2 = acc[i][j][2] + bx, v3 = acc[i][j][3] + by;
                *(float2*)(C + (size_t)rb * Ntot + col) = make_float2(v2, v3);
                s0 += v2; q0 += v2 * v2; s1 += v3; q1 += v3 * v3;
            }
        }
#pragma unroll
        for (int off = 4; off <= 16; off <<= 1) {
            s0 += __shfl_xor_sync(0xFFFFFFFFu, s0, off);
            s1 += __shfl_xor_sync(0xFFFFFFFFu, s1, off);
            q0 += __shfl_xor_sync(0xFFFFFFFFu, q0, off);
            q1 += __shfl_xor_sync(0xFFFFFFFFu, q1, off);
        }
        if (lane < 4) {
            atomicAdd(&s_sum[cloc],     s0);
            atomicAdd(&s_sum[cloc + 1], s1);
            atomicAdd(&s_sq[cloc],      q0);
            atomicAdd(&s_sq[cloc + 1],  q1);
        }
    }
    __syncthreads();
    if (tid < 128) {
        atomicAdd(&g_sum[n0 + tid],   s_sum[tid]);
        atomicAdd(&g_sumsq[n0 + tid], s_sq[tid]);
    }
}

// ---------------- BatchNorm (training mode) ------------------------------------
__global__ void zero_stats() {
    int c = blockIdx.x * blockDim.x + threadIdx.x;
    if (c < EMB2) { g_sum[c] = 0.f; g_sumsq[c] = 0.f; }
}
__global__ void bn_finalize(const float* __restrict__ gamma,
                            const float* __restrict__ beta, int C) {
    int c = blockIdx.x * blockDim.x + threadIdx.x;
    if (c >= C) return;
    float m = g_sum[c] * (1.f / N_NODES);
    float v = g_sumsq[c] * (1.f / N_NODES) - m * m;
    float inv = rsqrtf(v + BN_EPS);
    float sc = gamma[c] * inv;
    g_scale[c] = sc;
    g_shift[c] = beta[c] - sc * m;
}

// float4 grid-stride: hi/lo fp16 split output (GEMM2 input). C4 = C/4.
__global__ void bnrelu_split(const float* __restrict__ Z,
                             __half* __restrict__ Hi,
                             __half* __restrict__ Lo, int C4) {
    int total = N_NODES * C4;
    for (int i4 = blockIdx.x * blockDim.x + threadIdx.x; i4 < total;
         i4 += gridDim.x * blockDim.x) {
        int col = (i4 % C4) * 4;
        float4 z = ((const float4*)Z)[i4];
        float v[4];
        v[0] = fmaxf(g_scale[col]     * z.x + g_shift[col],     0.f);
        v[1] = fmaxf(g_scale[col + 1] * z.y + g_shift[col + 1], 0.f);
        v[2] = fmaxf(g_scale[col + 2] * z.z + g_shift[col + 2], 0.f);
        v[3] = fmaxf(g_scale[col + 3] * z.w + g_shift[col + 3], 0.f);
        __half hi[4], lo[4];
#pragma unroll
        for (int j = 0; j < 4; j++) {
            hi[j] = __float2half(v[j]);
            lo[j] = __float2half(v[j] - __half2float(hi[j]));
        }
        size_t base = (size_t)i4 * 4;
        *(__half2*)&Hi[base]     = __halves2half2(hi[0], hi[1]);
        *(__half2*)&Hi[base + 2] = __halves2half2(hi[2], hi[3]);
        *(__half2*)&Lo[base]     = __halves2half2(lo[0], lo[1]);
        *(__half2*)&Lo[base + 2] = __halves2half2(lo[2], lo[3]);
    }
}

// last layer only: h = relu(bn(z1)) -> d_out (GOFF region)
__global__ void bnrelu_out(const float* __restrict__ Z, float* __restrict__ O1) {
    const int C4 = EMB / 4;
    int total = N_NODES * C4;
    for (int i4 = blockIdx.x * blockDim.x + threadIdx.x; i4 < total;
         i4 += gridDim.x * blockDim.x) {
        int col = (i4 % C4) * 4;
        float4 z = ((const float4*)Z)[i4];
        float4 o;
        o.x = fmaxf(g_scale[col]     * z.x + g_shift[col],     0.f);
        o.y = fmaxf(g_scale[col + 1] * z.y + g_shift[col + 1], 0.f);
        o.z = fmaxf(g_scale[col + 2] * z.z + g_shift[col + 2], 0.f);
        o.w = fmaxf(g_scale[col + 3] * z.w + g_shift[col + 3], 0.f);
        ((float4*)O1)[i4] = o;
    }
}

// ---------------- pooling -------------------------------------------------------
__global__ void boundaries_kernel(const int* __restrict__ batch) {
    int g = threadIdx.x;
    if (g < NUM_GRAPHS) {
        int lo = 0, hi = N_NODES;
        while (lo < hi) {
            int mid = (lo + hi) >> 1;
            if (batch[mid] < g) lo = mid + 1; else hi = mid;
        }
        g_gstart[g] = lo;
    }
    if (g == 0) g_gstart[NUM_GRAPHS] = N_NODES;
}
__global__ void pool(const float* __restrict__ h, float* __restrict__ out) {
    int g = blockIdx.x, t = threadIdx.x;
    int s = g_gstart[g], e = g_gstart[g + 1];
    float a0 = 0.f, a1 = 0.f, a2 = 0.f;
    for (int r = s; r < e; r++) {
        const float* hr = h + (size_t)r * EMB;
        a0 += hr[t]; a1 += hr[t + 128]; a2 += hr[t + 256];
    }
    float* o = out + (size_t)g * EMB;
    o[t] = a0; o[t + 128] = a1; o[t + 256] = a2;
}

// ---------------- launch ----------------------------------------------------------
extern "C" void kernel_launch(void* const* d_in, const int* in_sizes, int n_in,
                              void* d_out, int out_size) {
    const int*   batch    = (const int*)d_in[0];
    const int*   x        = (const int*)d_in[1];
    const int*   ei       = (const int*)d_in[2];
    const int*   ea       = (const int*)d_in[3];
    const float* atom_emb = (const float*)d_in[4];
    const float* bond_emb = (const float*)d_in[5];
    const float* W1       = (const float*)d_in[6];
    const float* b1       = (const float*)d_in[7];
    const float* g1       = (const float*)d_in[8];
    const float* be1      = (const float*)d_in[9];
    const float* W2       = (const float*)d_in[10];
    const float* b2       = (const float*)d_in[11];
    const float* gbn      = (const float*)d_in[12];
    const float* bbn      = (const float*)d_in[13];
    float* out = (float*)d_out;

    float* g_h_p;   cudaGetSymbolAddress((void**)&g_h_p,  g_h);
    float* g_z1_p;  cudaGetSymbolAddress((void**)&g_z1_p, g_z1);
    float* g_z2_p;  cudaGetSymbolAddress((void**)&g_z2_p, g_z2);
    __half *Ahi_p, *Alo_p, *W1h_p, *W1l_p, *W2h_p, *W2l_p;
    cudaGetSymbolAddress((void**)&Ahi_p, g_Ahi);
    cudaGetSymbolAddress((void**)&Alo_p, g_Alo);
    cudaGetSymbolAddress((void**)&W1h_p, g_W1t_hi);
    cudaGetSymbolAddress((void**)&W1l_p, g_W1t_lo);
    cudaGetSymbolAddress((void**)&W2h_p, g_W2t_hi);
    cudaGetSymbolAddress((void**)&W2l_p, g_W2t_lo);

    cudaFuncSetAttribute(gemm_mma, cudaFuncAttributeMaxDynamicSharedMemorySize,
                         GEMM_SMEM);

    encode_nodes<<<N_NODES, 96>>>(x, atom_emb);
    build_ecombo<<<512, EMB>>>(bond_emb);

    zero_deg<<<NBLK, 256>>>();
    count_deg<<<(N_EDGES + 255) / 256, 256>>>(ei);
    deg_partial<<<NBLK, 256>>>();
    bsum_scan<<<1, 256>>>();
    rowptr_write<<<NBLK, 256>>>();
    fill_csr<<<(N_EDGES + 255) / 256, 256>>>(ei, ea);

    {
        dim3 g1d(EMB2 / 32, EMB / 32, NLAYER);
        wsplit<<<g1d, dim3(32, 8)>>>(W1, W1h_p, W1l_p, EMB, EMB2);
        dim3 g2d(EMB / 32, EMB2 / 32, NLAYER);
        wsplit<<<g2d, dim3(32, 8)>>>(W2, W2h_p, W2l_p, EMB2, EMB);
    }

    const int MT = (N_NODES + 127) / 128;  // 391
    const int EW_BLOCKS = 2368;

    for (int l = 0; l < NLAYER; l++) {
        // gather + fused outer-BN transform of previous layer (l>0)
        aggregate<<<N_NODES, 96>>>(l == 0 ? g_h_p : g_z1_p, l > 0);

        zero_stats<<<(EMB2 + 255) / 256, 256>>>();
        gemm_mma<<<dim3(EMB2 / 128, MT), 128, GEMM_SMEM>>>(
            Ahi_p, Alo_p,
            W1h_p + (size_t)l * EMB2 * EMB, W1l_p + (size_t)l * EMB2 * EMB,
            b1 + l * EMB2, g_z2_p, N_NODES, EMB2, EMB);
        bn_finalize<<<(EMB2 + 255) / 256, 256>>>(g1 + l * EMB2, be1 + l * EMB2, EMB2);
        bnrelu_split<<<EW_BLOCKS, 256>>>(g_z2_p, Ahi_p, Alo_p, EMB2 / 4);

        zero_stats<<<(EMB2 + 255) / 256, 256>>>();
        gemm_mma<<<dim3(EMB / 128, MT), 128, GEMM_SMEM>>>(
            Ahi_p, Alo_p,
            W2h_p + (size_t)l * EMB * EMB2, W2l_p + (size_t)l * EMB * EMB2,
            b2 + l * EMB, g_z1_p, N_NODES, EMB, EMB2);
        bn_finalize<<<(EMB + 255) / 256, 256>>>(gbn + l * EMB, bbn + l * EMB, EMB);
        // next aggregate applies the outer BN (layer l) on the fly
    }

    // final h = relu(bn(z1)) written once, directly into d_out
    bnrelu_out<<<EW_BLOCKS, 256>>>(g_z1_p, out + GOFF);
    boundaries_kernel<<<1, 128>>>(batch);
    pool<<<NUM_GRAPHS, 128>>>(out + GOFF, out);
}